// round 1
// baseline (speedup 1.0000x reference)
#include <cuda_runtime.h>
#include <math.h>

#define NN 512      // NUM_NEURONS
#define DM 512      // D_MODEL
#define TOK 1024    // 4*256 tokens

// k = LUT_SIZE / (2*pi), inv_k = 2*pi / LUT_SIZE (fp32-rounded, matching JAX f32 constants)
#define KF    651.8986469044033f
#define IKF   1.5339807878856412e-3f
#define I4096 2.44140625e-4f

// Scratch (static device globals — no runtime allocation allowed)
static __device__ float4 g_c4[DM * NN];    // [d][n] : {scale, bias*k, attn_cos, attn_sin}
static __device__ float2 g_sum[TOK * NN];  // [t][n] : {cos_sum, sin_sum}
static __device__ float  g_pcT[NN * DM];   // proj_cos_w transposed [n][d]
static __device__ float  g_psT[NN * DM];   // proj_sin_w transposed [n][d]

// ---------------------------------------------------------------------------
// Precompute: pack per-(n,d) constants transposed to [d][n]; transpose proj W.
// ---------------------------------------------------------------------------
__global__ void pre_k(const float* __restrict__ W, const float* __restrict__ B,
                      const float* __restrict__ AC, const float* __restrict__ AS,
                      const float* __restrict__ PC, const float* __restrict__ PS) {
    int i = blockIdx.x * blockDim.x + threadIdx.x;   // i = d*512 + n
    if (i >= NN * DM) return;
    int d = i >> 9;
    int n = i & (NN - 1);
    int s = n * DM + d;                               // [n][d] index into W/B/attn

    float4 v;
    v.x = KF / (1.0f + fabsf(W[s]));  // scale = k / wavelength
    v.y = B[s] * KF;                  // bias * k
    v.z = AC[s];
    v.w = AS[s];
    g_c4[i] = v;

    // proj weights are [d_model][num_neurons]; PC[i] = PC[d][n] -> PT[n][d]
    g_pcT[s] = PC[i];
    g_psT[s] = PS[i];
}

// ---------------------------------------------------------------------------
// Main kernel: for a tile of 4 tokens and 128 neurons, accumulate over d.
// grid = (256 token tiles, 4 neuron quarters), block = 128 threads (1 neuron each)
// ---------------------------------------------------------------------------
__global__ __launch_bounds__(128, 8) void main_k(const float* __restrict__ x) {
    __shared__ float4 xs[DM];   // xs[d] = {x[t0+0][d], x[t0+1][d], x[t0+2][d], x[t0+3][d]}

    const int t0 = blockIdx.x * 4;
    const int n  = blockIdx.y * 128 + threadIdx.x;

    // Stage x tile into shared, transposed to [d][t] float4
    float* xsf = (float*)xs;
    for (int i = threadIdx.x; i < 4 * DM; i += 128) {
        int t = i >> 9;
        int d = i & (DM - 1);
        xsf[d * 4 + t] = x[(t0 + t) * DM + d];
    }
    __syncthreads();

    float c0 = 0.f, c1 = 0.f, c2 = 0.f, c3 = 0.f;
    float s0 = 0.f, s1 = 0.f, s2 = 0.f, s3 = 0.f;

    const float4* __restrict__ p = g_c4 + n;

#define STEP(XT, CACC, SACC)                                    \
    {                                                           \
        float fq  = rintf(fmaf((XT), cv.x, cv.y));              \
        fq        = fmaf(rintf(fq * I4096), -4096.0f, fq);      \
        float ang = fq * IKF;                                   \
        float sv  = __sinf(ang);                                \
        float cc  = __cosf(ang);                                \
        CACC = fmaf(cc, cv.z, CACC);                            \
        SACC = fmaf(sv, cv.w, SACC);                            \
    }

#pragma unroll 2
    for (int d = 0; d < DM; d++) {
        float4 cv = p[d << 9];   // g_c4[d*512 + n], coalesced LDG.128
        float4 xv = xs[d];       // broadcast LDS.128
        STEP(xv.x, c0, s0);
        STEP(xv.y, c1, s1);
        STEP(xv.z, c2, s2);
        STEP(xv.w, c3, s3);
    }
#undef STEP

    g_sum[(t0 + 0) * NN + n] = make_float2(c0, s0);
    g_sum[(t0 + 1) * NN + n] = make_float2(c1, s1);
    g_sum[(t0 + 2) * NN + n] = make_float2(c2, s2);
    g_sum[(t0 + 3) * NN + n] = make_float2(c3, s3);
}

// ---------------------------------------------------------------------------
// Projection + SiLU: out[t][d] = silu( sum_n cs[t][n]*PcT[n][d] + ss[t][n]*PsT[n][d] )
// grid = (128 token tiles of 8, 2 d halves), block = 128 threads (2 d each)
// ---------------------------------------------------------------------------
#define GT 8
__global__ __launch_bounds__(128) void proj_k(float* __restrict__ out) {
    __shared__ float2 sh[GT * NN];   // 32 KB: {cos_sum, sin_sum} for 8 tokens x 512 n

    const int t0 = blockIdx.x * GT;
    const int dh = blockIdx.y * 128 + threadIdx.x;   // float2 index over d (d = 2*dh)

    for (int i = threadIdx.x; i < GT * NN; i += 128)
        sh[i] = g_sum[(t0 + (i >> 9)) * NN + (i & (NN - 1))];
    __syncthreads();

    float2 acc[GT];
#pragma unroll
    for (int t = 0; t < GT; t++) acc[t] = make_float2(0.f, 0.f);

    const float2* __restrict__ pc2 = (const float2*)g_pcT;
    const float2* __restrict__ ps2 = (const float2*)g_psT;

#pragma unroll 2
    for (int nn = 0; nn < NN; nn++) {
        float2 pc = pc2[nn * (DM / 2) + dh];
        float2 ps = ps2[nn * (DM / 2) + dh];
#pragma unroll
        for (int t = 0; t < GT; t++) {
            float2 cs = sh[t * NN + nn];
            acc[t].x = fmaf(cs.x, pc.x, fmaf(cs.y, ps.x, acc[t].x));
            acc[t].y = fmaf(cs.x, pc.y, fmaf(cs.y, ps.y, acc[t].y));
        }
    }

#pragma unroll
    for (int t = 0; t < GT; t++) {
        float2 o = acc[t];
        o.x = o.x / (1.0f + __expf(-o.x));
        o.y = o.y / (1.0f + __expf(-o.y));
        reinterpret_cast<float2*>(out)[(t0 + t) * (DM / 2) + dh] = o;
    }
}

// ---------------------------------------------------------------------------
// Launch
// ---------------------------------------------------------------------------
extern "C" void kernel_launch(void* const* d_in, const int* in_sizes, int n_in,
                              void* d_out, int out_size) {
    const float* x  = (const float*)d_in[0];
    const float* W  = (const float*)d_in[1];
    const float* B  = (const float*)d_in[2];
    const float* AC = (const float*)d_in[3];
    const float* AS = (const float*)d_in[4];
    const float* PC = (const float*)d_in[5];
    const float* PS = (const float*)d_in[6];
    // d_in[7]/d_in[8] (sin/cos tables) are reproduced analytically via MUFU.

    pre_k<<<(NN * DM + 511) / 512, 512>>>(W, B, AC, AS, PC, PS);

    dim3 gm(TOK / 4, 4);
    main_k<<<gm, 128>>>(x);

    dim3 gp(TOK / GT, DM / 256);
    proj_k<<<gp, 128>>>((float*)d_out);
}

// round 2
// speedup vs baseline: 1.6685x; 1.6685x over previous
#include <cuda_runtime.h>
#include <math.h>

#define NN 512      // NUM_NEURONS
#define DM 512      // D_MODEL
#define TOK 1024    // 4*256 tokens

// k = LUT_SIZE / (2*pi), inv_k = 2*pi / LUT_SIZE
#define KF    651.8986469044033f
#define IKF   1.5339807878856412e-3f
#define MAGIC 12582912.0f   // 1.5 * 2^23 : RNE rounding constant

// Scratch (static device globals — no runtime allocation allowed)
static __device__ float4 g_c4[DM * NN];    // [d][n] : {k/wavelength, B*k, attn_cos, attn_sin}
static __device__ float2 g_sum[TOK * NN];  // [t][n] : {cos_sum, sin_sum}
static __device__ float  g_pcT[NN * DM];   // proj_cos_w transposed [n][d]
static __device__ float  g_psT[NN * DM];   // proj_sin_w transposed [n][d]

// ---------------------------------------------------------------------------
// Precompute (tiled transpose, coalesced in and out).
// Block = (32,8); each block owns a 32x32 (n,d) tile.
// ---------------------------------------------------------------------------
__global__ __launch_bounds__(256) void pre_k(
        const float* __restrict__ W,  const float* __restrict__ B,
        const float* __restrict__ AC, const float* __restrict__ AS,
        const float* __restrict__ PC, const float* __restrict__ PS) {
    __shared__ float sW[32][33], sB[32][33], sC[32][33], sS[32][33];
    __shared__ float sPC[32][33], sPS[32][33];

    const int n0 = blockIdx.y * 32;
    const int d0 = blockIdx.x * 32;
    const int tx = threadIdx.x, ty = threadIdx.y;

#pragma unroll
    for (int k = 0; k < 4; k++) {
        int r = ty + 8 * k;
        int gi = (n0 + r) * DM + d0 + tx;   // [n][d] coalesced along d
        sW[r][tx] = W[gi];
        sB[r][tx] = B[gi];
        sC[r][tx] = AC[gi];
        sS[r][tx] = AS[gi];
        int gp = (d0 + r) * NN + n0 + tx;   // [d][n] coalesced along n
        sPC[r][tx] = PC[gp];
        sPS[r][tx] = PS[gp];
    }
    __syncthreads();

#pragma unroll
    for (int k = 0; k < 4; k++) {
        int r = ty + 8 * k;
        // g_c4[(d0+r)*512 + (n0+tx)] : coalesced float4 stores along n
        float4 v;
        v.x = KF / (1.0f + fabsf(sW[tx][r]));
        v.y = sB[tx][r] * KF;
        v.z = sC[tx][r];
        v.w = sS[tx][r];
        g_c4[(d0 + r) * NN + n0 + tx] = v;
        // proj transposes: [d][n] -> [n][d], coalesced along d
        g_pcT[(n0 + r) * DM + d0 + tx] = sPC[tx][r];
        g_psT[(n0 + r) * DM + d0 + tx] = sPS[tx][r];
    }
}

// ---------------------------------------------------------------------------
// Main kernel: tile of 4 tokens x 128 neurons, accumulate over d.
// grid = (256 token tiles, 4 neuron quarters), block = 128 (1 neuron each).
// Hot path per element: FFMA + 2 FADD (RNE round) + FMUL + 2 MUFU + 2 FFMA.
// XU pipe: exactly 2 ops/element (the MUFU sin/cos) -> pipe floor ~227K cyc/SMSP.
// ---------------------------------------------------------------------------
__global__ __launch_bounds__(128, 8) void main_k(const float* __restrict__ x) {
    __shared__ float4 xs[DM];   // xs[d] = {x[t0..t0+3][d]}

    const int t0 = blockIdx.x * 4;
    const int n  = blockIdx.y * 128 + threadIdx.x;

    float* xsf = (float*)xs;
    for (int i = threadIdx.x; i < 4 * DM; i += 128) {
        int t = i >> 9;
        int d = i & (DM - 1);
        xsf[d * 4 + t] = x[(t0 + t) * DM + d];
    }
    __syncthreads();

    float c0 = 0.f, c1 = 0.f, c2 = 0.f, c3 = 0.f;
    float s0 = 0.f, s1 = 0.f, s2 = 0.f, s3 = 0.f;

    const float4* __restrict__ p = g_c4 + n;

#define STEP(XT, CACC, SACC)                                    \
    {                                                           \
        float t  = fmaf((XT), cv.x, cv.y) + MAGIC;  /* RNE */   \
        float fq = t - MAGIC;                                   \
        float ang = fq * IKF;                                   \
        float sv = __sinf(ang);                                 \
        float cc = __cosf(ang);                                 \
        CACC = fmaf(cc, cv.z, CACC);                            \
        SACC = fmaf(sv, cv.w, SACC);                            \
    }

#pragma unroll 4
    for (int d = 0; d < DM; d++) {
        float4 cv = p[d << 9];   // g_c4[d*512 + n], coalesced LDG.128, L2-resident
        float4 xv = xs[d];       // broadcast LDS.128
        STEP(xv.x, c0, s0);
        STEP(xv.y, c1, s1);
        STEP(xv.z, c2, s2);
        STEP(xv.w, c3, s3);
    }
#undef STEP

    g_sum[(t0 + 0) * NN + n] = make_float2(c0, s0);
    g_sum[(t0 + 1) * NN + n] = make_float2(c1, s1);
    g_sum[(t0 + 2) * NN + n] = make_float2(c2, s2);
    g_sum[(t0 + 3) * NN + n] = make_float2(c3, s3);
}

// ---------------------------------------------------------------------------
// Projection + SiLU: out[t][d] = silu( sum_n cs*PcT[n][d] + ss*PsT[n][d] )
// grid = (128 token tiles of 8, 2 d halves), block = 128 threads (2 d each)
// ---------------------------------------------------------------------------
#define GT 8
__global__ __launch_bounds__(128) void proj_k(float* __restrict__ out) {
    __shared__ float2 sh[GT * NN];   // 32 KB

    const int t0 = blockIdx.x * GT;
    const int dh = blockIdx.y * 128 + threadIdx.x;

    for (int i = threadIdx.x; i < GT * NN; i += 128)
        sh[i] = g_sum[(t0 + (i >> 9)) * NN + (i & (NN - 1))];
    __syncthreads();

    float2 acc[GT];
#pragma unroll
    for (int t = 0; t < GT; t++) acc[t] = make_float2(0.f, 0.f);

    const float2* __restrict__ pc2 = (const float2*)g_pcT;
    const float2* __restrict__ ps2 = (const float2*)g_psT;

#pragma unroll 2
    for (int nn = 0; nn < NN; nn++) {
        float2 pc = pc2[nn * (DM / 2) + dh];
        float2 ps = ps2[nn * (DM / 2) + dh];
#pragma unroll
        for (int t = 0; t < GT; t++) {
            float2 cs = sh[t * NN + nn];
            acc[t].x = fmaf(cs.x, pc.x, fmaf(cs.y, ps.x, acc[t].x));
            acc[t].y = fmaf(cs.x, pc.y, fmaf(cs.y, ps.y, acc[t].y));
        }
    }

#pragma unroll
    for (int t = 0; t < GT; t++) {
        float2 o = acc[t];
        o.x = o.x / (1.0f + __expf(-o.x));
        o.y = o.y / (1.0f + __expf(-o.y));
        reinterpret_cast<float2*>(out)[(t0 + t) * (DM / 2) + dh] = o;
    }
}

// ---------------------------------------------------------------------------
// Launch
// ---------------------------------------------------------------------------
extern "C" void kernel_launch(void* const* d_in, const int* in_sizes, int n_in,
                              void* d_out, int out_size) {
    const float* x  = (const float*)d_in[0];
    const float* W  = (const float*)d_in[1];
    const float* B  = (const float*)d_in[2];
    const float* AC = (const float*)d_in[3];
    const float* AS = (const float*)d_in[4];
    const float* PC = (const float*)d_in[5];
    const float* PS = (const float*)d_in[6];
    // d_in[7]/d_in[8] (sin/cos tables) reproduced analytically (periodicity + MUFU).

    dim3 bt(32, 8);
    dim3 gt(DM / 32, NN / 32);
    pre_k<<<gt, bt>>>(W, B, AC, AS, PC, PS);

    dim3 gm(TOK / 4, 4);
    main_k<<<gm, 128>>>(x);

    dim3 gp(TOK / GT, DM / 256);
    proj_k<<<gp, 128>>>((float*)d_out);
}

// round 3
// speedup vs baseline: 1.6903x; 1.0130x over previous
#include <cuda_runtime.h>
#include <math.h>

#define NN 512      // NUM_NEURONS
#define DM 512      // D_MODEL
#define TOK 1024    // 4*256 tokens

// k = LUT_SIZE / (2*pi), inv_k = 2*pi / LUT_SIZE
#define KF    651.8986469044033f
#define IKF   1.5339807878856412e-3f
#define MAGIC 12582912.0f   // 1.5 * 2^23 : RNE rounding constant

// Scratch (static device globals — no runtime allocation allowed)
static __device__ float4 g_c4[DM * NN];    // [d][n] : {k/wl, B*k + MAGIC, attn_cos, attn_sin}
static __device__ float2 g_sum[TOK * NN];  // [t][n] : {cos_sum, sin_sum}
static __device__ float  g_pcT[NN * DM];   // proj_cos_w transposed [n][d]
static __device__ float  g_psT[NN * DM];   // proj_sin_w transposed [n][d]

// ---------------------------------------------------------------------------
// Precompute (tiled transpose, coalesced in and out).
// ---------------------------------------------------------------------------
__global__ __launch_bounds__(256) void pre_k(
        const float* __restrict__ W,  const float* __restrict__ B,
        const float* __restrict__ AC, const float* __restrict__ AS,
        const float* __restrict__ PC, const float* __restrict__ PS) {
    __shared__ float sW[32][33], sB[32][33], sC[32][33], sS[32][33];
    __shared__ float sPC[32][33], sPS[32][33];

    const int n0 = blockIdx.y * 32;
    const int d0 = blockIdx.x * 32;
    const int tx = threadIdx.x, ty = threadIdx.y;

#pragma unroll
    for (int k = 0; k < 4; k++) {
        int r = ty + 8 * k;
        int gi = (n0 + r) * DM + d0 + tx;
        sW[r][tx] = W[gi];
        sB[r][tx] = B[gi];
        sC[r][tx] = AC[gi];
        sS[r][tx] = AS[gi];
        int gp = (d0 + r) * NN + n0 + tx;
        sPC[r][tx] = PC[gp];
        sPS[r][tx] = PS[gp];
    }
    __syncthreads();

#pragma unroll
    for (int k = 0; k < 4; k++) {
        int r = ty + 8 * k;
        float4 v;
        v.x = KF / (1.0f + fabsf(sW[tx][r]));
        v.y = fmaf(sB[tx][r], KF, MAGIC);   // bias*k folded with RNE magic constant
        v.z = sC[tx][r];
        v.w = sS[tx][r];
        g_c4[(d0 + r) * NN + n0 + tx] = v;
        g_pcT[(n0 + r) * DM + d0 + tx] = sPC[tx][r];
        g_psT[(n0 + r) * DM + d0 + tx] = sPS[tx][r];
    }
}

// ---------------------------------------------------------------------------
// Main kernel: tile of 4 tokens x 128 neurons, accumulate over d.
// grid = (256 token tiles, 4 neuron quarters), block = 128 (1 neuron each).
// Per element: FFMA(round) + FSUB + FMUL + 2 MUFU + 2 FFMA  = 5 FMA-pipe + 2 XU.
// XU floor: 227K cyc/SMSP; FMA 142K; issue ~104K — XU-bound by design.
// ---------------------------------------------------------------------------
__global__ __launch_bounds__(128, 8) void main_k(const float* __restrict__ x) {
    __shared__ float4 xs[DM];   // xs[d] = {x[t0..t0+3][d]}

    const int t0 = blockIdx.x * 4;
    const int n  = blockIdx.y * 128 + threadIdx.x;

    float* xsf = (float*)xs;
    for (int i = threadIdx.x; i < 4 * DM; i += 128) {
        int t = i >> 9;
        int d = i & (DM - 1);
        xsf[d * 4 + t] = x[(t0 + t) * DM + d];
    }
    __syncthreads();

    float c0 = 0.f, c1 = 0.f, c2 = 0.f, c3 = 0.f;
    float s0 = 0.f, s1 = 0.f, s2 = 0.f, s3 = 0.f;

    const float4* __restrict__ p = g_c4 + n;

#define STEP(XT, CACC, SACC)                                        \
    {                                                               \
        float t   = fmaf((XT), cv.x, cv.y);  /* RNE round in FMA */ \
        float fq  = t - MAGIC;               /* integer-valued  */  \
        float ang = fq * IKF;                                       \
        float sv  = __sinf(ang);                                    \
        float cc  = __cosf(ang);                                    \
        CACC = fmaf(cc, cv.z, CACC);                                \
        SACC = fmaf(sv, cv.w, SACC);                                \
    }

#pragma unroll 8
    for (int d = 0; d < DM; d++) {
        float4 cv = p[d << 9];   // coalesced LDG.128, L2-resident, MLP=8 via unroll
        float4 xv = xs[d];       // broadcast LDS.128
        STEP(xv.x, c0, s0);
        STEP(xv.y, c1, s1);
        STEP(xv.z, c2, s2);
        STEP(xv.w, c3, s3);
    }
#undef STEP

    g_sum[(t0 + 0) * NN + n] = make_float2(c0, s0);
    g_sum[(t0 + 1) * NN + n] = make_float2(c1, s1);
    g_sum[(t0 + 2) * NN + n] = make_float2(c2, s2);
    g_sum[(t0 + 3) * NN + n] = make_float2(c3, s3);
}

// ---------------------------------------------------------------------------
// Projection + SiLU: out[t][d] = silu( sum_n cs*PcT[n][d] + ss*PsT[n][d] )
// grid = (128 token tiles of 8, 2 d halves), block = 128 threads (2 d each)
// ---------------------------------------------------------------------------
#define GT 8
__global__ __launch_bounds__(128) void proj_k(float* __restrict__ out) {
    __shared__ float2 sh[GT * NN];   // 32 KB

    const int t0 = blockIdx.x * GT;
    const int dh = blockIdx.y * 128 + threadIdx.x;

    for (int i = threadIdx.x; i < GT * NN; i += 128)
        sh[i] = g_sum[(t0 + (i >> 9)) * NN + (i & (NN - 1))];
    __syncthreads();

    float2 acc[GT];
#pragma unroll
    for (int t = 0; t < GT; t++) acc[t] = make_float2(0.f, 0.f);

    const float2* __restrict__ pc2 = (const float2*)g_pcT;
    const float2* __restrict__ ps2 = (const float2*)g_psT;

#pragma unroll 2
    for (int nn = 0; nn < NN; nn++) {
        float2 pc = pc2[nn * (DM / 2) + dh];
        float2 ps = ps2[nn * (DM / 2) + dh];
#pragma unroll
        for (int t = 0; t < GT; t++) {
            float2 cs = sh[t * NN + nn];
            acc[t].x = fmaf(cs.x, pc.x, fmaf(cs.y, ps.x, acc[t].x));
            acc[t].y = fmaf(cs.x, pc.y, fmaf(cs.y, ps.y, acc[t].y));
        }
    }

#pragma unroll
    for (int t = 0; t < GT; t++) {
        float2 o = acc[t];
        o.x = o.x / (1.0f + __expf(-o.x));
        o.y = o.y / (1.0f + __expf(-o.y));
        reinterpret_cast<float2*>(out)[(t0 + t) * (DM / 2) + dh] = o;
    }
}

// ---------------------------------------------------------------------------
// Launch
// ---------------------------------------------------------------------------
extern "C" void kernel_launch(void* const* d_in, const int* in_sizes, int n_in,
                              void* d_out, int out_size) {
    const float* x  = (const float*)d_in[0];
    const float* W  = (const float*)d_in[1];
    const float* B  = (const float*)d_in[2];
    const float* AC = (const float*)d_in[3];
    const float* AS = (const float*)d_in[4];
    const float* PC = (const float*)d_in[5];
    const float* PS = (const float*)d_in[6];
    // d_in[7]/d_in[8] (sin/cos tables) reproduced analytically (periodicity + MUFU).

    dim3 bt(32, 8);
    dim3 gt(DM / 32, NN / 32);
    pre_k<<<gt, bt>>>(W, B, AC, AS, PC, PS);

    dim3 gm(TOK / 4, 4);
    main_k<<<gm, 128>>>(x);

    dim3 gp(TOK / GT, DM / 256);
    proj_k<<<gp, 128>>>((float*)d_out);
}